// round 15
// baseline (speedup 1.0000x reference)
#include <cuda_runtime.h>
#include <math.h>

#define NU 20000
#define NI 20000
#define NN 20000         // NU == NI
#define NC (2*NN)        // combined node space: [0,NN)=drug/item side, [NN,2NN)=gene/user side
#define D  256
#define NNZc 600000
#define EEc  300000
#define EA   (2*EEc)     // combined attention edges
#define EZ   (2*NNZc)    // combined spmm edge slots
#define NB   8192
#define DROPSCALE (1.0f/0.9f)

// ---------------- device scratch (static allocation, allowed) ----------------
__device__ __align__(16) float g_h[NC*D];   // combined h = [E_d_0; E_g_0] @ att_W
__device__ float g_s1[NC];
__device__ float g_s2[NC];
__device__ __align__(16) float g_Ed0[NI*D];
__device__ __align__(16) float g_Eg0[NU*D];
__device__ __align__(16) float g_Eg[NU*D];
__device__ __align__(16) float g_Ed[NI*D];
__device__ int   g_deg[NC];
__device__ int   g_off[NC+1];
__device__ int   g_cur[NC];
__device__ int   g_eidx[EZ];         // CSR payload: att = src node id; spmm = other node id
__device__ float g_w[EZ];            // CSR payload (spmm only): dropout-masked scaled value
__device__ int   g_key[EZ];
__device__ int   g_srcA[EA];
__device__ unsigned char g_need[NC];
__device__ __align__(16) float g_h1[2*NB*D];
__device__ __align__(16) float g_h2[2*NB*D];
__device__ float g_sc[2*NB];     // [0:NB) pos scores, [NB:2NB) neg scores
__device__ float g_part[256];
__device__ float g_sums[4];
__device__ int   g_dropWide;     // 1 if drop arrays are 4-byte elements, 0 if 1-byte

// ---------------- drop dtype detector ----------------
// For 4-byte encodings (int32 0/1 or float32 0.0/1.0) every byte at offset
// (4k+1) is 0. For uint8 bools ~90% of them are nonzero.
__global__ void k_dropdetect(const unsigned char* __restrict__ drop, int* __restrict__ flag)
{
    __shared__ int cnt;
    if (threadIdx.x == 0) cnt = 0;
    __syncthreads();
    int nz = 0;
    for (int j = threadIdx.x; j < 1024; j += blockDim.x)
        nz += (drop[4 * j + 1] != 0);
    atomicAdd(&cnt, nz);
    __syncthreads();
    if (threadIdx.x == 0) *flag = (cnt == 0) ? 1 : 0;
}

// ---------------- SGEMM: C[M,N] = A[M,K] @ B[K,N] (+bias, relu) ----------------
// 128x128 tile, BK=8, 256 threads, 8x8 per thread.
__global__ __launch_bounds__(256) void k_sgemm(
    const float* __restrict__ A, const float* __restrict__ Bw,
    float* __restrict__ C, int M, int N, int K,
    const float* __restrict__ bias, int relu)
{
    __shared__ float As[8][132];
    __shared__ float Bs[8][128];
    int tid = threadIdx.x;
    int bx = blockIdx.x, by = blockIdx.y;
    int aRow = tid >> 1, aCol = (tid & 1) * 4;
    int bRow = tid >> 5, bCol = (tid & 31) * 4;
    int rowBase = (tid >> 4) * 8;
    int colBase = (tid & 15) * 8;
    float acc[8][8];
    #pragma unroll
    for (int i = 0; i < 8; i++)
        #pragma unroll
        for (int j = 0; j < 8; j++) acc[i][j] = 0.f;

    int gRow = by * 128 + aRow;
    bool aValid = gRow < M;
    const float* Aptr = A + (size_t)(aValid ? gRow : 0) * K;

    for (int k0 = 0; k0 < K; k0 += 8) {
        float4 av = aValid ? *(const float4*)(Aptr + k0 + aCol)
                           : make_float4(0.f, 0.f, 0.f, 0.f);
        As[aCol+0][aRow] = av.x; As[aCol+1][aRow] = av.y;
        As[aCol+2][aRow] = av.z; As[aCol+3][aRow] = av.w;
        float4 bv = *(const float4*)(Bw + (size_t)(k0 + bRow) * N + bx * 128 + bCol);
        *(float4*)(&Bs[bRow][bCol]) = bv;
        __syncthreads();
        #pragma unroll
        for (int k = 0; k < 8; k++) {
            float4 a0 = *(const float4*)&As[k][rowBase];
            float4 a1 = *(const float4*)&As[k][rowBase+4];
            float4 b0 = *(const float4*)&Bs[k][colBase];
            float4 b1 = *(const float4*)&Bs[k][colBase+4];
            float ra[8] = {a0.x,a0.y,a0.z,a0.w,a1.x,a1.y,a1.z,a1.w};
            float rb[8] = {b0.x,b0.y,b0.z,b0.w,b1.x,b1.y,b1.z,b1.w};
            #pragma unroll
            for (int i = 0; i < 8; i++)
                #pragma unroll
                for (int j = 0; j < 8; j++) acc[i][j] += ra[i] * rb[j];
        }
        __syncthreads();
    }
    #pragma unroll
    for (int i = 0; i < 8; i++) {
        int r = by * 128 + rowBase + i;
        if (r >= M) continue;
        #pragma unroll
        for (int j = 0; j < 8; j++) {
            int c = bx * 128 + colBase + j;
            float v = acc[i][j];
            if (bias) v += bias[c];
            if (relu) v = fmaxf(v, 0.f);
            C[(size_t)r * N + c] = v;
        }
    }
}

// SGEMM over the stacked input [A0; A1] (M = 2*NN): row r<NN -> A0[r], else A1[r-NN].
__global__ __launch_bounds__(256) void k_sgemm_sel(
    const float* __restrict__ A0, const float* __restrict__ A1,
    const float* __restrict__ Bw, float* __restrict__ C,
    int M, int N, int K)
{
    __shared__ float As[8][132];
    __shared__ float Bs[8][128];
    int tid = threadIdx.x;
    int bx = blockIdx.x, by = blockIdx.y;
    int aRow = tid >> 1, aCol = (tid & 1) * 4;
    int bRow = tid >> 5, bCol = (tid & 31) * 4;
    int rowBase = (tid >> 4) * 8;
    int colBase = (tid & 15) * 8;
    float acc[8][8];
    #pragma unroll
    for (int i = 0; i < 8; i++)
        #pragma unroll
        for (int j = 0; j < 8; j++) acc[i][j] = 0.f;

    int gRow = by * 128 + aRow;
    bool aValid = gRow < M;
    int rr = aValid ? gRow : 0;
    const float* Aptr = (rr < NN) ? (A0 + (size_t)rr * K)
                                  : (A1 + (size_t)(rr - NN) * K);

    for (int k0 = 0; k0 < K; k0 += 8) {
        float4 av = aValid ? *(const float4*)(Aptr + k0 + aCol)
                           : make_float4(0.f, 0.f, 0.f, 0.f);
        As[aCol+0][aRow] = av.x; As[aCol+1][aRow] = av.y;
        As[aCol+2][aRow] = av.z; As[aCol+3][aRow] = av.w;
        float4 bv = *(const float4*)(Bw + (size_t)(k0 + bRow) * N + bx * 128 + bCol);
        *(float4*)(&Bs[bRow][bCol]) = bv;
        __syncthreads();
        #pragma unroll
        for (int k = 0; k < 8; k++) {
            float4 a0 = *(const float4*)&As[k][rowBase];
            float4 a1 = *(const float4*)&As[k][rowBase+4];
            float4 b0 = *(const float4*)&Bs[k][colBase];
            float4 b1 = *(const float4*)&Bs[k][colBase+4];
            float ra[8] = {a0.x,a0.y,a0.z,a0.w,a1.x,a1.y,a1.z,a1.w};
            float rb[8] = {b0.x,b0.y,b0.z,b0.w,b1.x,b1.y,b1.z,b1.w};
            #pragma unroll
            for (int i = 0; i < 8; i++)
                #pragma unroll
                for (int j = 0; j < 8; j++) acc[i][j] += ra[i] * rb[j];
        }
        __syncthreads();
    }
    #pragma unroll
    for (int i = 0; i < 8; i++) {
        int r = by * 128 + rowBase + i;
        if (r >= M) continue;
        #pragma unroll
        for (int j = 0; j < 8; j++) {
            int c = bx * 128 + colBase + j;
            C[(size_t)r * N + c] = acc[i][j];
        }
    }
}

// SGEMM with gathered concat A rows over the fused pos+neg batch (M = 2*NB):
//   row r -> [ Au[uids[r & (NB-1)]] , (r < NB ? Ap[pos[r]] : Ap[neg[r-NB]]) ]
__global__ __launch_bounds__(256) void k_sgemm_gather(
    const float* __restrict__ Au, const float* __restrict__ Ap,
    const int* __restrict__ uids, const int* __restrict__ posI,
    const int* __restrict__ negI,
    const float* __restrict__ Bw, float* __restrict__ C,
    int M, int N, int K, const float* __restrict__ bias, int relu)
{
    __shared__ float As[8][132];
    __shared__ float Bs[8][128];
    int tid = threadIdx.x;
    int bx = blockIdx.x, by = blockIdx.y;
    int aRow = tid >> 1, aCol = (tid & 1) * 4;
    int bRow = tid >> 5, bCol = (tid & 31) * 4;
    int rowBase = (tid >> 4) * 8;
    int colBase = (tid & 15) * 8;
    float acc[8][8];
    #pragma unroll
    for (int i = 0; i < 8; i++)
        #pragma unroll
        for (int j = 0; j < 8; j++) acc[i][j] = 0.f;

    int gRow = by * 128 + aRow;
    bool aValid = gRow < M;
    int rr = aValid ? gRow : 0;
    int iu = uids[rr & (NB - 1)];
    int ip = (rr < NB) ? posI[rr] : negI[rr - NB];
    const float* rowU = Au + (size_t)iu * D;
    const float* rowP = Ap + (size_t)ip * D;

    for (int k0 = 0; k0 < K; k0 += 8) {
        int kc = k0 + aCol;
        const float* src = (kc < D) ? (rowU + kc) : (rowP + (kc - D));
        float4 av = aValid ? *(const float4*)src : make_float4(0.f,0.f,0.f,0.f);
        As[aCol+0][aRow] = av.x; As[aCol+1][aRow] = av.y;
        As[aCol+2][aRow] = av.z; As[aCol+3][aRow] = av.w;
        float4 bv = *(const float4*)(Bw + (size_t)(k0 + bRow) * N + bx * 128 + bCol);
        *(float4*)(&Bs[bRow][bCol]) = bv;
        __syncthreads();
        #pragma unroll
        for (int k = 0; k < 8; k++) {
            float4 a0 = *(const float4*)&As[k][rowBase];
            float4 a1 = *(const float4*)&As[k][rowBase+4];
            float4 b0 = *(const float4*)&Bs[k][colBase];
            float4 b1 = *(const float4*)&Bs[k][colBase+4];
            float ra[8] = {a0.x,a0.y,a0.z,a0.w,a1.x,a1.y,a1.z,a1.w};
            float rb[8] = {b0.x,b0.y,b0.z,b0.w,b1.x,b1.y,b1.z,b1.w};
            #pragma unroll
            for (int i = 0; i < 8; i++)
                #pragma unroll
                for (int j = 0; j < 8; j++) acc[i][j] += ra[i] * rb[j];
        }
        __syncthreads();
    }
    #pragma unroll
    for (int i = 0; i < 8; i++) {
        int r = by * 128 + rowBase + i;
        if (r >= M) continue;
        #pragma unroll
        for (int j = 0; j < 8; j++) {
            int c = bx * 128 + colBase + j;
            float v = acc[i][j];
            if (bias) v += bias[c];
            if (relu) v = fmaxf(v, 0.f);
            C[(size_t)r * N + c] = v;
        }
    }
}

// ---------------- per-row dots s1 = h.a[:D], s2 = h.a[D:] ----------------
__global__ void k_rowdots(const float* __restrict__ h, const float* __restrict__ a,
                          float* __restrict__ s1, float* __restrict__ s2, int n)
{
    int row = blockIdx.x * 8 + (threadIdx.x >> 5);
    if (row >= n) return;
    int lane = threadIdx.x & 31;
    const float* hr = h + (size_t)row * D;
    float d1 = 0.f, d2 = 0.f;
    #pragma unroll
    for (int k = lane; k < D; k += 32) {
        float hv = hr[k];
        d1 += hv * a[k];
        d2 += hv * a[D + k];
    }
    #pragma unroll
    for (int o = 16; o; o >>= 1) {
        d1 += __shfl_xor_sync(0xffffffffu, d1, o);
        d2 += __shfl_xor_sync(0xffffffffu, d2, o);
    }
    if (!lane) { s1[row] = d1; s2[row] = d2; }
}

// ---------------- fused key building + degree histogram ----------------
// Attention: e<EEc -> drug edge e (tgt/src in [0,NN)); else gene edge e-EEc, +NN.
// Requires deg[] zeroed beforehand.
__global__ void k_keys_hist_att(const int* __restrict__ drugE, const int* __restrict__ geneE,
                                int* __restrict__ key, int* __restrict__ srcA,
                                int* __restrict__ deg)
{
    int e = blockIdx.x * blockDim.x + threadIdx.x;
    if (e >= EA) return;
    int k, s;
    if (e < EEc) {
        k = drugE[EEc + e];
        s = drugE[e];
    } else {
        int i = e - EEc;
        k = geneE[EEc + i] + NN;
        s = geneE[i] + NN;
    }
    key[e]  = k;
    srcA[e] = s;
    atomicAdd(&deg[k], 1);
}

// SPMM: slot i<NNZ -> key adj_rows[i] (E_g side); slot i>=NNZ -> adj_cols[i-NNZ]+NN.
// Requires deg[] zeroed beforehand.
__global__ void k_keys_hist_spmm(const int* __restrict__ rows, const int* __restrict__ cols,
                                 int* __restrict__ key, int* __restrict__ deg)
{
    int e = blockIdx.x * blockDim.x + threadIdx.x;
    if (e >= EZ) return;
    int k = (e < NNZc) ? rows[e] : (cols[e - NNZc] + NN);
    key[e] = k;
    atomicAdd(&deg[k], 1);
}

// Single-block shuffle-based exclusive scan (1024 threads).
__global__ __launch_bounds__(1024) void k_scan(const int* __restrict__ deg,
                                               int* __restrict__ off,
                                               int* __restrict__ cur, int n)
{
    __shared__ int wsum[32];
    __shared__ int carry;
    int tid = threadIdx.x;
    int lane = tid & 31, wid = tid >> 5;
    if (tid == 0) carry = 0;
    __syncthreads();
    for (int base = 0; base < n; base += 1024) {
        int i = base + tid;
        int v = (i < n) ? deg[i] : 0;
        int x = v;
        #pragma unroll
        for (int o = 1; o < 32; o <<= 1) {
            int t = __shfl_up_sync(0xffffffffu, x, o);
            if (lane >= o) x += t;
        }
        if (lane == 31) wsum[wid] = x;
        __syncthreads();
        if (wid == 0) {
            int s = wsum[lane];
            #pragma unroll
            for (int o = 1; o < 32; o <<= 1) {
                int t = __shfl_up_sync(0xffffffffu, s, o);
                if (lane >= o) s += t;
            }
            wsum[lane] = s;
        }
        __syncthreads();
        int incl = x + (wid ? wsum[wid - 1] : 0);
        int ex = carry + incl - v;
        if (i < n) { off[i] = ex; cur[i] = ex; }
        __syncthreads();
        if (tid == 0) carry += wsum[31];
        __syncthreads();
    }
    if (tid == 0) off[n] = carry;
}

// Attention scatter: stores the SOURCE NODE ID as the CSR payload (agg never
// needs the edge id itself) -> one fewer dependent load in the agg loop.
__global__ void k_scatter_att(const int* __restrict__ keys, const int* __restrict__ srcA,
                              int* __restrict__ cur, int* __restrict__ eidx)
{
    int i = blockIdx.x * blockDim.x + threadIdx.x;
    if (i >= EA) return;
    int p = atomicAdd(&cur[keys[i]], 1);
    eidx[p] = srcA[i];
}

// SPMM scatter: stores {other node id, dropout-masked scaled value} as payload.
__global__ void k_scatter_spmm(const int* __restrict__ keys,
                               const int* __restrict__ adj_rows,
                               const int* __restrict__ adj_cols,
                               const float* __restrict__ vals,
                               const unsigned char* __restrict__ drop1,
                               const unsigned char* __restrict__ drop2,
                               const int* __restrict__ dropWide,
                               int* __restrict__ cur,
                               int* __restrict__ eidx, float* __restrict__ wArr)
{
    int i = blockIdx.x * blockDim.x + threadIdx.x;
    if (i >= EZ) return;
    int wide = *dropWide;
    bool isU = i < NNZc;
    int orig = isU ? i : (i - NNZc);
    const unsigned char* drop = isU ? drop1 : drop2;
    int keep = wide ? (((const int*)drop)[orig] != 0) : (drop[orig] != 0);
    float w = keep ? (vals[orig] * DROPSCALE) : 0.f;
    int other = isU ? adj_cols[orig] : adj_rows[orig];
    int p = atomicAdd(&cur[keys[i]], 1);
    eidx[p] = other;
    wArr[p] = w;
}

// ---------------- attention aggregation over combined nodes ----------------
// eidx[k] IS the source node id (payload scatter). Lane owns 8 CONTIGUOUS
// columns (lane*8 .. lane*8+7) -> 2x LDG.128 per visited row instead of 8x LDG.32.
__global__ void k_att_agg(const float* __restrict__ X0a, const float* __restrict__ X0b,
                          const float* __restrict__ s1, const float* __restrict__ s2,
                          const float* __restrict__ h,
                          const int* __restrict__ off, const int* __restrict__ eidx,
                          float* __restrict__ Ea, float* __restrict__ Eb)
{
    int node = blockIdx.x * 8 + (threadIdx.x >> 5);
    if (node >= NC) return;
    int lane = threadIdx.x & 31;
    int c0 = lane * 8;                 // this lane's 8 contiguous columns
    bool isA = node < NN;
    const float* X0 = isA ? (X0a + (size_t)node * D) : (X0b + (size_t)(node - NN) * D);
    float* Eout = isA ? (Ea + (size_t)node * D) : (Eb + (size_t)(node - NN) * D);
    int st = off[node], en = off[node + 1];
    float4 o0, o1;
    if (st == en) {
        o0 = *(const float4*)(X0 + c0);
        o1 = *(const float4*)(X0 + c0 + 4);
    } else {
        float s2n = s2[node];
        float mx = -1e30f;
        for (int k = st + lane; k < en; k += 32) {
            float v = s1[eidx[k]] + s2n;
            v = fmaxf(v, 0.2f * v);       // leaky_relu(., 0.2)
            mx = fmaxf(mx, v);
        }
        #pragma unroll
        for (int o = 16; o; o >>= 1) mx = fmaxf(mx, __shfl_xor_sync(0xffffffffu, mx, o));
        float denom = 0.f;
        float4 a0 = make_float4(0.f,0.f,0.f,0.f);
        float4 a1 = make_float4(0.f,0.f,0.f,0.f);
        for (int k = st; k < en; k++) {
            int s = eidx[k];
            float v = s1[s] + s2n;
            v = fmaxf(v, 0.2f * v);
            float w = expf(v - mx);
            denom += w;
            const float* hr = h + (size_t)s * D + c0;
            float4 h0 = *(const float4*)hr;
            float4 h1 = *(const float4*)(hr + 4);
            a0.x += w * h0.x; a0.y += w * h0.y; a0.z += w * h0.z; a0.w += w * h0.w;
            a1.x += w * h1.x; a1.y += w * h1.y; a1.z += w * h1.z; a1.w += w * h1.w;
        }
        float inv = 0.1f / (denom + 1e-9f);
        float4 x0 = *(const float4*)(X0 + c0);
        float4 x1 = *(const float4*)(X0 + c0 + 4);
        o0.x = a0.x * inv + x0.x; o0.y = a0.y * inv + x0.y;
        o0.z = a0.z * inv + x0.z; o0.w = a0.w * inv + x0.w;
        o1.x = a1.x * inv + x1.x; o1.y = a1.y * inv + x1.y;
        o1.z = a1.z * inv + x1.z; o1.w = a1.w * inv + x1.w;
    }
    *(float4*)(Eout + c0) = o0;
    *(float4*)(Eout + c0 + 4) = o1;
}

// ---------------- combined SPMM (payload CSR, needed rows only) ----------------
// Lane owns 8 contiguous columns -> 2x LDG.128 per edge per lane.
__global__ void k_spmm(const float* __restrict__ Ed0, const float* __restrict__ Eg0,
                       const unsigned char* __restrict__ need,
                       const int* __restrict__ off, const int* __restrict__ eidx,
                       const float* __restrict__ wArr,
                       float* __restrict__ OutG, float* __restrict__ OutD)
{
    int row = blockIdx.x * 8 + (threadIdx.x >> 5);
    if (row >= NC) return;
    if (!need[row]) return;
    int lane = threadIdx.x & 31;
    int c0 = lane * 8;
    bool isU = row < NN;   // E_g side
    const float* Xin = isU ? Ed0 : Eg0;
    float* Out = isU ? (OutG + (size_t)row * D) : (OutD + (size_t)(row - NN) * D);
    int st = off[row], en = off[row + 1];
    float4 a0 = make_float4(0.f,0.f,0.f,0.f);
    float4 a1 = make_float4(0.f,0.f,0.f,0.f);
    for (int k = st; k < en; k++) {
        float v = wArr[k];
        if (v == 0.f) continue;
        const float* xr = Xin + (size_t)eidx[k] * D + c0;
        float4 x0 = *(const float4*)xr;
        float4 x1 = *(const float4*)(xr + 4);
        a0.x += v * x0.x; a0.y += v * x0.y; a0.z += v * x0.z; a0.w += v * x0.w;
        a1.x += v * x1.x; a1.y += v * x1.y; a1.z += v * x1.z; a1.w += v * x1.w;
    }
    *(float4*)(Out + c0) = a0;
    *(float4*)(Out + c0 + 4) = a1;
}

__global__ void k_mark(const int* __restrict__ ids, int n, int base,
                       unsigned char* __restrict__ need)
{
    int i = blockIdx.x * blockDim.x + threadIdx.x;
    if (i < n) need[base + ids[i]] = 1;
}

// ---------------- final MLP layer over fused batch: sc = h2 . w3 + b3 ----------------
__global__ void k_dotw3(const float* __restrict__ h2, const float* __restrict__ w3,
                        const float* __restrict__ b3, float* __restrict__ out, int m)
{
    int b = blockIdx.x * 8 + (threadIdx.x >> 5);
    if (b >= m) return;
    int lane = threadIdx.x & 31;
    const float* r = h2 + (size_t)b * D;
    float s = 0.f;
    #pragma unroll
    for (int k = lane; k < D; k += 32) s += r[k] * w3[k];
    #pragma unroll
    for (int o = 16; o; o >>= 1) s += __shfl_xor_sync(0xffffffffu, s, o);
    if (!lane) out[b] = s + b3[0];
}

// ---------------- losses ----------------
__device__ __forceinline__ float softplusf(float x)
{
    return fmaxf(x, 0.f) + log1pf(expf(-fabsf(x)));
}

__global__ __launch_bounds__(1024) void k_loss(const float* __restrict__ sc,
                                               float* __restrict__ sums)
{
    __shared__ float sh0[1024], sh1[1024], sh2[1024];
    float lp = 0.f, ln = 0.f, lb = 0.f;
    for (int b = threadIdx.x; b < NB; b += 1024) {
        float p = sc[b], q = sc[NB + b];
        lp += softplusf(-p);
        ln += softplusf(q);
        lb += softplusf(-(p - q));
    }
    sh0[threadIdx.x] = lp; sh1[threadIdx.x] = ln; sh2[threadIdx.x] = lb;
    __syncthreads();
    for (int o = 512; o; o >>= 1) {
        if (threadIdx.x < o) {
            sh0[threadIdx.x] += sh0[threadIdx.x + o];
            sh1[threadIdx.x] += sh1[threadIdx.x + o];
            sh2[threadIdx.x] += sh2[threadIdx.x + o];
        }
        __syncthreads();
    }
    if (threadIdx.x == 0) { sums[0] = sh0[0]; sums[1] = sh1[0]; sums[2] = sh2[0]; }
}

// ---------------- regularization sum of squares over 16 params ----------------
__global__ void k_reg(const float* p0, const float* p1, const float* p2, const float* p3,
                      const float* p4, const float* p5, const float* p6, const float* p7,
                      const float* p8, const float* p9, const float* p10, const float* p11,
                      const float* p12, const float* p13, const float* p14, const float* p15,
                      float* __restrict__ part)
{
    const float* ptrs[16] = {p0,p1,p2,p3,p4,p5,p6,p7,p8,p9,p10,p11,p12,p13,p14,p15};
    const int sz[16] = {NU*D, NI*D, D*D, 2*D, D*D, 2*D, 2*D*D, D,
                        D*D, D, D, 1, 2*D*D, D, D*D, D};
    int gid = blockIdx.x * blockDim.x + threadIdx.x;
    int gsz = gridDim.x * blockDim.x;
    float a = 0.f;
    #pragma unroll
    for (int s = 0; s < 16; s++) {
        const float* p = ptrs[s];
        int n = sz[s];
        for (int i = gid; i < n; i += gsz) { float v = p[i]; a += v * v; }
    }
    __shared__ float sh[256];
    sh[threadIdx.x] = a;
    __syncthreads();
    for (int o = 128; o; o >>= 1) {
        if (threadIdx.x < o) sh[threadIdx.x] += sh[threadIdx.x + o];
        __syncthreads();
    }
    if (threadIdx.x == 0) part[blockIdx.x] = sh[0];
}

__global__ void k_final(const float* __restrict__ part, const float* __restrict__ sums,
                        float* __restrict__ out)
{
    __shared__ float sh[256];
    sh[threadIdx.x] = part[threadIdx.x];
    __syncthreads();
    for (int o = 128; o; o >>= 1) {
        if (threadIdx.x < o) sh[threadIdx.x] += sh[threadIdx.x + o];
        __syncthreads();
    }
    if (threadIdx.x == 0) {
        float reg = sh[0] * 1e-7f;
        float lr = (sums[0] + sums[1] + sums[2]) / (float)NB;
        out[0] = reg + lr;
        out[1] = lr;
        out[2] = 0.f;
    }
}

// ---------------- host ----------------
extern "C" void kernel_launch(void* const* d_in, const int* in_sizes, int n_in,
                              void* d_out, int out_size)
{
    const float* E_g_0  = (const float*)d_in[0];
    const float* E_d_0  = (const float*)d_in[1];
    const float* att_W  = (const float*)d_in[2];
    const float* att_a  = (const float*)d_in[3];
    const float* att1_W = (const float*)d_in[4];
    const float* att1_a = (const float*)d_in[5];
    const float* W1     = (const float*)d_in[6];
    const float* b1     = (const float*)d_in[7];
    const float* W2     = (const float*)d_in[8];
    const float* b2     = (const float*)d_in[9];
    const float* W3     = (const float*)d_in[10];
    const float* b3     = (const float*)d_in[11];
    const float* M1     = (const float*)d_in[12];
    const float* mb1    = (const float*)d_in[13];
    const float* M2     = (const float*)d_in[14];
    const float* mb2    = (const float*)d_in[15];
    const float* adj_vals = (const float*)d_in[16];
    const int* uids = (const int*)d_in[17];
    const int* pos  = (const int*)d_in[19];
    const int* neg  = (const int*)d_in[20];
    const int* gene_edges = (const int*)d_in[21];
    const int* drug_edges = (const int*)d_in[22];
    const int* adj_rows = (const int*)d_in[23];
    const int* adj_cols = (const int*)d_in[24];
    const unsigned char* drop1 = (const unsigned char*)d_in[25];
    const unsigned char* drop2 = (const unsigned char*)d_in[26];
    float* out = (float*)d_out;

    // symbol addresses for scratch
    float *p_h, *p_s1, *p_s2, *p_Ed0, *p_Eg0, *p_Eg, *p_Ed;
    float *p_h1, *p_h2, *p_sc, *p_part, *p_sums, *p_w;
    int *p_deg, *p_off, *p_cur, *p_eidx, *p_key, *p_srcA, *p_dw;
    unsigned char *p_need;
    cudaGetSymbolAddress((void**)&p_h, g_h);
    cudaGetSymbolAddress((void**)&p_s1, g_s1);
    cudaGetSymbolAddress((void**)&p_s2, g_s2);
    cudaGetSymbolAddress((void**)&p_Ed0, g_Ed0);
    cudaGetSymbolAddress((void**)&p_Eg0, g_Eg0);
    cudaGetSymbolAddress((void**)&p_Eg, g_Eg);
    cudaGetSymbolAddress((void**)&p_Ed, g_Ed);
    cudaGetSymbolAddress((void**)&p_deg, g_deg);
    cudaGetSymbolAddress((void**)&p_off, g_off);
    cudaGetSymbolAddress((void**)&p_cur, g_cur);
    cudaGetSymbolAddress((void**)&p_eidx, g_eidx);
    cudaGetSymbolAddress((void**)&p_w, g_w);
    cudaGetSymbolAddress((void**)&p_key, g_key);
    cudaGetSymbolAddress((void**)&p_srcA, g_srcA);
    cudaGetSymbolAddress((void**)&p_need, g_need);
    cudaGetSymbolAddress((void**)&p_h1, g_h1);
    cudaGetSymbolAddress((void**)&p_h2, g_h2);
    cudaGetSymbolAddress((void**)&p_sc, g_sc);
    cudaGetSymbolAddress((void**)&p_part, g_part);
    cudaGetSymbolAddress((void**)&p_sums, g_sums);
    cudaGetSymbolAddress((void**)&p_dw, g_dropWide);

    dim3 gGemmAtt(2, (NC + 127) / 128);       // combined 40000-row SGEMM
    dim3 gGemmMlp(2, (2 * NB + 127) / 128);   // fused pos+neg batch
    int rowBlocksC = (NC + 7) / 8;            // warp-per-row over combined nodes
    int eaBlocks = (EA + 255) / 256;
    int ezBlocks = (EZ + 255) / 256;
    int bBlocks  = (NB + 255) / 256;

    // ---- drop dtype detection (drop1 and drop2 share dtype) ----
    k_dropdetect<<<1, 256>>>(drop1, p_dw);

    // ---- combined attention: h = [E_d_0; E_g_0] @ att_W ----
    k_sgemm_sel<<<gGemmAtt, 256>>>(E_d_0, E_g_0, att_W, p_h, NC, D, D);
    k_rowdots<<<rowBlocksC, 256>>>(p_h, att_a, p_s1, p_s2, NC);

    // combined attention CSR (targets in [0,2NN)), payload = src node id
    cudaMemsetAsync(p_deg, 0, NC * sizeof(int));
    k_keys_hist_att<<<eaBlocks, 256>>>(drug_edges, gene_edges, p_key, p_srcA, p_deg);
    k_scan<<<1, 1024>>>(p_deg, p_off, p_cur, NC);
    k_scatter_att<<<eaBlocks, 256>>>(p_key, p_srcA, p_cur, p_eidx);
    k_att_agg<<<rowBlocksC, 256>>>(E_d_0, E_g_0, p_s1, p_s2, p_h,
                                   p_off, p_eidx, p_Ed0, p_Eg0);

    // ---- needed-row mask over combined space ----
    cudaMemsetAsync(p_need, 0, NC);
    k_mark<<<bBlocks, 256>>>(uids, NB, 0, p_need);
    k_mark<<<bBlocks, 256>>>(pos,  NB, NN, p_need);
    k_mark<<<bBlocks, 256>>>(neg,  NB, NN, p_need);

    // ---- combined SPMM CSR: keys = [adj_rows ; adj_cols+NN], payload = {other, w} ----
    cudaMemsetAsync(p_deg, 0, NC * sizeof(int));
    k_keys_hist_spmm<<<ezBlocks, 256>>>(adj_rows, adj_cols, p_key, p_deg);
    k_scan<<<1, 1024>>>(p_deg, p_off, p_cur, NC);
    k_scatter_spmm<<<ezBlocks, 256>>>(p_key, adj_rows, adj_cols, adj_vals,
                                      drop1, drop2, p_dw, p_cur, p_eidx, p_w);
    k_spmm<<<rowBlocksC, 256>>>(p_Ed0, p_Eg0, p_need, p_off, p_eidx, p_w,
                                p_Eg, p_Ed);

    // ---- fused pos+neg MLP (batch 2*NB) ----
    k_sgemm_gather<<<gGemmMlp, 256>>>(p_Eg, p_Ed, uids, pos, neg, W1, p_h1,
                                      2 * NB, D, 2 * D, b1, 1);
    k_sgemm<<<gGemmMlp, 256>>>(p_h1, W2, p_h2, 2 * NB, D, D, b2, 1);
    k_dotw3<<<(2 * NB + 7) / 8, 256>>>(p_h2, W3, b3, p_sc, 2 * NB);

    // ---- losses ----
    k_loss<<<1, 1024>>>(p_sc, p_sums);
    k_reg<<<256, 256>>>(E_g_0, E_d_0, att_W, att_a, att1_W, att1_a, W1, b1,
                        W2, b2, W3, b3, M1, mb1, M2, mb2, p_part);
    k_final<<<1, 256>>>(p_part, p_sums, out);
}

// round 16
// speedup vs baseline: 1.2295x; 1.2295x over previous
#include <cuda_runtime.h>
#include <mma.h>
#include <math.h>
using namespace nvcuda;

#define NU 20000
#define NI 20000
#define NN 20000         // NU == NI
#define NC (2*NN)        // combined node space
#define D  256
#define NNZc 600000
#define EEc  300000
#define EA   (2*EEc)
#define EZ   (2*NNZc)
#define NB   8192
#define DROPSCALE (1.0f/0.9f)

// ---------------- device scratch ----------------
__device__ __align__(16) float g_h[NC*D];
__device__ float g_s1[NC];
__device__ float g_s2[NC];
__device__ __align__(16) float g_Ed0[NI*D];
__device__ __align__(16) float g_Eg0[NU*D];
__device__ __align__(16) float g_Eg[NU*D];
__device__ __align__(16) float g_Ed[NI*D];
__device__ int   g_deg[NC];
__device__ int   g_off[NC+1];
__device__ int   g_cur[NC];
__device__ int   g_eidx[EZ];
__device__ float g_w[EZ];
__device__ int   g_key[EZ];
__device__ int   g_srcA[EA];
__device__ unsigned char g_need[NC];
__device__ __align__(16) float g_h1[2*NB*D];
__device__ __align__(16) float g_h2[2*NB*D];
__device__ float g_sc[2*NB];
__device__ float g_part[256];
__device__ float g_sums[4];
__device__ int   g_dropWide;

// ---------------- drop dtype detector ----------------
__global__ void k_dropdetect(const unsigned char* __restrict__ drop, int* __restrict__ flag)
{
    __shared__ int cnt;
    if (threadIdx.x == 0) cnt = 0;
    __syncthreads();
    int nz = 0;
    for (int j = threadIdx.x; j < 1024; j += blockDim.x)
        nz += (drop[4 * j + 1] != 0);
    atomicAdd(&cnt, nz);
    __syncthreads();
    if (threadIdx.x == 0) *flag = (cnt == 0) ? 1 : 0;
}

// ---------------- tf32 tensor-core GEMM ----------------
// C[M,N] = A[M,K] @ B[K,N] (+bias, relu). 128x128 tile, BK=16, 256 threads.
// 8 warps in 4(m) x 2(n); warp tile 32x64 = 2x4 m16n16k8 accumulators.
// MODE 0: plain A.  MODE 1: stacked [A0;A1] split at NN.
// MODE 2: gathered concat rows over fused pos+neg batch (K = 2*D).
template<int MODE>
__global__ __launch_bounds__(256) void k_tf32gemm(
    const float* __restrict__ A0, const float* __restrict__ A1,
    const int* __restrict__ uids, const int* __restrict__ posI,
    const int* __restrict__ negI,
    const float* __restrict__ Bw, float* __restrict__ C,
    int M, int N, int K, const float* __restrict__ bias, int relu)
{
    __shared__ float As[128*20];   // [row][k] ldm=20
    __shared__ float Bs[16*132];   // [k][n]  ldm=132 (reused for bias tile in epilogue)
    __shared__ float stage[8*256]; // per-warp 16x16 staging for partial tiles

    int tid = threadIdx.x;
    int bx = blockIdx.x, by = blockIdx.y;
    int wid = tid >> 5, lane = tid & 31;
    int warp_m = wid & 3, warp_n = wid >> 2;

    wmma::fragment<wmma::accumulator,16,16,8,float> acc[2][4];
    #pragma unroll
    for (int mi = 0; mi < 2; mi++)
        #pragma unroll
        for (int ni = 0; ni < 4; ni++) wmma::fill_fragment(acc[mi][ni], 0.f);

    int rowIn = tid >> 1;                // 0..127 within tile
    int gRow = by * 128 + rowIn;
    bool aValid = gRow < M;
    int rr = aValid ? gRow : 0;
    const float* baseU;
    const float* baseP = nullptr;
    if (MODE == 0) {
        baseU = A0 + (size_t)rr * K;
    } else if (MODE == 1) {
        baseU = (rr < NN) ? (A0 + (size_t)rr * K) : (A1 + (size_t)(rr - NN) * K);
    } else {
        int iu = uids[rr & (NB - 1)];
        int ip = (rr < NB) ? posI[rr] : negI[rr - NB];
        baseU = A0 + (size_t)iu * D;
        baseP = A1 + (size_t)ip * D;
    }
    int c0 = (tid & 1) * 8;              // this thread's 8-col chunk within BK=16
    int bRow = tid >> 4;                 // 0..15
    int bCol = (tid & 15) * 8;

    for (int k0 = 0; k0 < K; k0 += 16) {
        float4 a0v, a1v;
        if (aValid) {
            const float* src;
            if (MODE == 2) {
                int kc = k0 + c0;        // 8-chunk never straddles the concat boundary (256 is 8-aligned)
                src = (kc < D) ? (baseU + kc) : (baseP + (kc - D));
            } else {
                src = baseU + k0 + c0;
            }
            a0v = *(const float4*)src;
            a1v = *(const float4*)(src + 4);
        } else {
            a0v = make_float4(0.f, 0.f, 0.f, 0.f);
            a1v = a0v;
        }
        *(float4*)(&As[rowIn * 20 + c0])     = a0v;
        *(float4*)(&As[rowIn * 20 + c0 + 4]) = a1v;
        const float* bp = Bw + (size_t)(k0 + bRow) * N + bx * 128 + bCol;
        *(float4*)(&Bs[bRow * 132 + bCol])     = *(const float4*)bp;
        *(float4*)(&Bs[bRow * 132 + bCol + 4]) = *(const float4*)(bp + 4);
        __syncthreads();

        #pragma unroll
        for (int ks = 0; ks < 16; ks += 8) {
            wmma::fragment<wmma::matrix_a,16,16,8,wmma::precision::tf32,wmma::row_major> af[2];
            wmma::fragment<wmma::matrix_b,16,16,8,wmma::precision::tf32,wmma::row_major> bf[4];
            #pragma unroll
            for (int mi = 0; mi < 2; mi++) {
                wmma::load_matrix_sync(af[mi], &As[(warp_m * 32 + mi * 16) * 20 + ks], 20);
                #pragma unroll
                for (int i = 0; i < af[mi].num_elements; i++)
                    af[mi].x[i] = wmma::__float_to_tf32(af[mi].x[i]);
            }
            #pragma unroll
            for (int ni = 0; ni < 4; ni++) {
                wmma::load_matrix_sync(bf[ni], &Bs[ks * 132 + warp_n * 64 + ni * 16], 132);
                #pragma unroll
                for (int i = 0; i < bf[ni].num_elements; i++)
                    bf[ni].x[i] = wmma::__float_to_tf32(bf[ni].x[i]);
            }
            #pragma unroll
            for (int mi = 0; mi < 2; mi++)
                #pragma unroll
                for (int ni = 0; ni < 4; ni++)
                    wmma::mma_sync(acc[mi][ni], af[mi], bf[ni], acc[mi][ni]);
        }
        __syncthreads();
    }

    // ---- epilogue: bias (via replicated tile loaded as accumulator frag), relu, store ----
    if (bias) {
        for (int i = tid; i < 16 * 128; i += 256) {
            int rrow = i >> 7, ccol = i & 127;
            Bs[rrow * 132 + ccol] = bias[bx * 128 + ccol];
        }
        __syncthreads();
    }
    bool full = (by * 128 + 128) <= M;
    float* st = &stage[wid * 256];
    #pragma unroll
    for (int ni = 0; ni < 4; ni++) {
        wmma::fragment<wmma::accumulator,16,16,8,float> bfrag;
        if (bias)
            wmma::load_matrix_sync(bfrag, &Bs[warp_n * 64 + ni * 16], 132, wmma::mem_row_major);
        #pragma unroll
        for (int mi = 0; mi < 2; mi++) {
            if (bias) {
                #pragma unroll
                for (int i = 0; i < acc[mi][ni].num_elements; i++)
                    acc[mi][ni].x[i] += bfrag.x[i];
            }
            if (relu) {
                #pragma unroll
                for (int i = 0; i < acc[mi][ni].num_elements; i++)
                    acc[mi][ni].x[i] = fmaxf(acc[mi][ni].x[i], 0.f);
            }
            int r0 = by * 128 + warp_m * 32 + mi * 16;
            int c0g = bx * 128 + warp_n * 64 + ni * 16;
            if (full) {
                wmma::store_matrix_sync(&C[(size_t)r0 * N + c0g], acc[mi][ni], N,
                                        wmma::mem_row_major);
            } else {
                wmma::store_matrix_sync(st, acc[mi][ni], 16, wmma::mem_row_major);
                __syncwarp();
                for (int e = lane; e < 256; e += 32) {
                    int er = e >> 4, ec = e & 15;
                    int gr = r0 + er;
                    if (gr < M) C[(size_t)gr * N + c0g + ec] = st[e];
                }
                __syncwarp();
            }
        }
    }
}

// ---------------- per-row dots s1 = h.a[:D], s2 = h.a[D:] ----------------
__global__ void k_rowdots(const float* __restrict__ h, const float* __restrict__ a,
                          float* __restrict__ s1, float* __restrict__ s2, int n)
{
    int row = blockIdx.x * 8 + (threadIdx.x >> 5);
    if (row >= n) return;
    int lane = threadIdx.x & 31;
    const float* hr = h + (size_t)row * D;
    float d1 = 0.f, d2 = 0.f;
    #pragma unroll
    for (int k = lane; k < D; k += 32) {
        float hv = hr[k];
        d1 += hv * a[k];
        d2 += hv * a[D + k];
    }
    #pragma unroll
    for (int o = 16; o; o >>= 1) {
        d1 += __shfl_xor_sync(0xffffffffu, d1, o);
        d2 += __shfl_xor_sync(0xffffffffu, d2, o);
    }
    if (!lane) { s1[row] = d1; s2[row] = d2; }
}

// ---------------- fused key building + degree histogram ----------------
__global__ void k_keys_hist_att(const int* __restrict__ drugE, const int* __restrict__ geneE,
                                int* __restrict__ key, int* __restrict__ srcA,
                                int* __restrict__ deg)
{
    int e = blockIdx.x * blockDim.x + threadIdx.x;
    if (e >= EA) return;
    int k, s;
    if (e < EEc) {
        k = drugE[EEc + e];
        s = drugE[e];
    } else {
        int i = e - EEc;
        k = geneE[EEc + i] + NN;
        s = geneE[i] + NN;
    }
    key[e]  = k;
    srcA[e] = s;
    atomicAdd(&deg[k], 1);
}

__global__ void k_keys_hist_spmm(const int* __restrict__ rows, const int* __restrict__ cols,
                                 int* __restrict__ key, int* __restrict__ deg)
{
    int e = blockIdx.x * blockDim.x + threadIdx.x;
    if (e >= EZ) return;
    int k = (e < NNZc) ? rows[e] : (cols[e - NNZc] + NN);
    key[e] = k;
    atomicAdd(&deg[k], 1);
}

// Single-block shuffle-based exclusive scan (1024 threads).
__global__ __launch_bounds__(1024) void k_scan(const int* __restrict__ deg,
                                               int* __restrict__ off,
                                               int* __restrict__ cur, int n)
{
    __shared__ int wsum[32];
    __shared__ int carry;
    int tid = threadIdx.x;
    int lane = tid & 31, wid = tid >> 5;
    if (tid == 0) carry = 0;
    __syncthreads();
    for (int base = 0; base < n; base += 1024) {
        int i = base + tid;
        int v = (i < n) ? deg[i] : 0;
        int x = v;
        #pragma unroll
        for (int o = 1; o < 32; o <<= 1) {
            int t = __shfl_up_sync(0xffffffffu, x, o);
            if (lane >= o) x += t;
        }
        if (lane == 31) wsum[wid] = x;
        __syncthreads();
        if (wid == 0) {
            int s = wsum[lane];
            #pragma unroll
            for (int o = 1; o < 32; o <<= 1) {
                int t = __shfl_up_sync(0xffffffffu, s, o);
                if (lane >= o) s += t;
            }
            wsum[lane] = s;
        }
        __syncthreads();
        int incl = x + (wid ? wsum[wid - 1] : 0);
        int ex = carry + incl - v;
        if (i < n) { off[i] = ex; cur[i] = ex; }
        __syncthreads();
        if (tid == 0) carry += wsum[31];
        __syncthreads();
    }
    if (tid == 0) off[n] = carry;
}

__global__ void k_scatter_att(const int* __restrict__ keys, const int* __restrict__ srcA,
                              int* __restrict__ cur, int* __restrict__ eidx)
{
    int i = blockIdx.x * blockDim.x + threadIdx.x;
    if (i >= EA) return;
    int p = atomicAdd(&cur[keys[i]], 1);
    eidx[p] = srcA[i];
}

__global__ void k_scatter_spmm(const int* __restrict__ keys,
                               const int* __restrict__ adj_rows,
                               const int* __restrict__ adj_cols,
                               const float* __restrict__ vals,
                               const unsigned char* __restrict__ drop1,
                               const unsigned char* __restrict__ drop2,
                               const int* __restrict__ dropWide,
                               int* __restrict__ cur,
                               int* __restrict__ eidx, float* __restrict__ wArr)
{
    int i = blockIdx.x * blockDim.x + threadIdx.x;
    if (i >= EZ) return;
    int wide = *dropWide;
    bool isU = i < NNZc;
    int orig = isU ? i : (i - NNZc);
    const unsigned char* drop = isU ? drop1 : drop2;
    int keep = wide ? (((const int*)drop)[orig] != 0) : (drop[orig] != 0);
    float w = keep ? (vals[orig] * DROPSCALE) : 0.f;
    int other = isU ? adj_cols[orig] : adj_rows[orig];
    int p = atomicAdd(&cur[keys[i]], 1);
    eidx[p] = other;
    wArr[p] = w;
}

// ---------------- attention aggregation (payload CSR, float4 lanes) ----------------
__global__ void k_att_agg(const float* __restrict__ X0a, const float* __restrict__ X0b,
                          const float* __restrict__ s1, const float* __restrict__ s2,
                          const float* __restrict__ h,
                          const int* __restrict__ off, const int* __restrict__ eidx,
                          float* __restrict__ Ea, float* __restrict__ Eb)
{
    int node = blockIdx.x * 8 + (threadIdx.x >> 5);
    if (node >= NC) return;
    int lane = threadIdx.x & 31;
    int c0 = lane * 8;
    bool isA = node < NN;
    const float* X0 = isA ? (X0a + (size_t)node * D) : (X0b + (size_t)(node - NN) * D);
    float* Eout = isA ? (Ea + (size_t)node * D) : (Eb + (size_t)(node - NN) * D);
    int st = off[node], en = off[node + 1];
    float4 o0, o1;
    if (st == en) {
        o0 = *(const float4*)(X0 + c0);
        o1 = *(const float4*)(X0 + c0 + 4);
    } else {
        float s2n = s2[node];
        float mx = -1e30f;
        for (int k = st + lane; k < en; k += 32) {
            float v = s1[eidx[k]] + s2n;
            v = fmaxf(v, 0.2f * v);
            mx = fmaxf(mx, v);
        }
        #pragma unroll
        for (int o = 16; o; o >>= 1) mx = fmaxf(mx, __shfl_xor_sync(0xffffffffu, mx, o));
        float denom = 0.f;
        float4 a0 = make_float4(0.f,0.f,0.f,0.f);
        float4 a1 = make_float4(0.f,0.f,0.f,0.f);
        for (int k = st; k < en; k++) {
            int s = eidx[k];
            float v = s1[s] + s2n;
            v = fmaxf(v, 0.2f * v);
            float w = expf(v - mx);
            denom += w;
            const float* hr = h + (size_t)s * D + c0;
            float4 h0 = *(const float4*)hr;
            float4 h1 = *(const float4*)(hr + 4);
            a0.x += w * h0.x; a0.y += w * h0.y; a0.z += w * h0.z; a0.w += w * h0.w;
            a1.x += w * h1.x; a1.y += w * h1.y; a1.z += w * h1.z; a1.w += w * h1.w;
        }
        float inv = 0.1f / (denom + 1e-9f);
        float4 x0 = *(const float4*)(X0 + c0);
        float4 x1 = *(const float4*)(X0 + c0 + 4);
        o0.x = a0.x * inv + x0.x; o0.y = a0.y * inv + x0.y;
        o0.z = a0.z * inv + x0.z; o0.w = a0.w * inv + x0.w;
        o1.x = a1.x * inv + x1.x; o1.y = a1.y * inv + x1.y;
        o1.z = a1.z * inv + x1.z; o1.w = a1.w * inv + x1.w;
    }
    *(float4*)(Eout + c0) = o0;
    *(float4*)(Eout + c0 + 4) = o1;
}

// ---------------- combined SPMM (payload CSR, needed rows only) ----------------
__global__ void k_spmm(const float* __restrict__ Ed0, const float* __restrict__ Eg0,
                       const unsigned char* __restrict__ need,
                       const int* __restrict__ off, const int* __restrict__ eidx,
                       const float* __restrict__ wArr,
                       float* __restrict__ OutG, float* __restrict__ OutD)
{
    int row = blockIdx.x * 8 + (threadIdx.x >> 5);
    if (row >= NC) return;
    if (!need[row]) return;
    int lane = threadIdx.x & 31;
    int c0 = lane * 8;
    bool isU = row < NN;
    const float* Xin = isU ? Ed0 : Eg0;
    float* Out = isU ? (OutG + (size_t)row * D) : (OutD + (size_t)(row - NN) * D);
    int st = off[row], en = off[row + 1];
    float4 a0 = make_float4(0.f,0.f,0.f,0.f);
    float4 a1 = make_float4(0.f,0.f,0.f,0.f);
    for (int k = st; k < en; k++) {
        float v = wArr[k];
        if (v == 0.f) continue;
        const float* xr = Xin + (size_t)eidx[k] * D + c0;
        float4 x0 = *(const float4*)xr;
        float4 x1 = *(const float4*)(xr + 4);
        a0.x += v * x0.x; a0.y += v * x0.y; a0.z += v * x0.z; a0.w += v * x0.w;
        a1.x += v * x1.x; a1.y += v * x1.y; a1.z += v * x1.z; a1.w += v * x1.w;
    }
    *(float4*)(Out + c0) = a0;
    *(float4*)(Out + c0 + 4) = a1;
}

__global__ void k_mark(const int* __restrict__ ids, int n, int base,
                       unsigned char* __restrict__ need)
{
    int i = blockIdx.x * blockDim.x + threadIdx.x;
    if (i < n) need[base + ids[i]] = 1;
}

// ---------------- final MLP layer: sc = h2 . w3 + b3 ----------------
__global__ void k_dotw3(const float* __restrict__ h2, const float* __restrict__ w3,
                        const float* __restrict__ b3, float* __restrict__ out, int m)
{
    int b = blockIdx.x * 8 + (threadIdx.x >> 5);
    if (b >= m) return;
    int lane = threadIdx.x & 31;
    const float* r = h2 + (size_t)b * D;
    float s = 0.f;
    #pragma unroll
    for (int k = lane; k < D; k += 32) s += r[k] * w3[k];
    #pragma unroll
    for (int o = 16; o; o >>= 1) s += __shfl_xor_sync(0xffffffffu, s, o);
    if (!lane) out[b] = s + b3[0];
}

// ---------------- losses ----------------
__device__ __forceinline__ float softplusf(float x)
{
    return fmaxf(x, 0.f) + log1pf(expf(-fabsf(x)));
}

__global__ __launch_bounds__(1024) void k_loss(const float* __restrict__ sc,
                                               float* __restrict__ sums)
{
    __shared__ float sh0[1024], sh1[1024], sh2[1024];
    float lp = 0.f, ln = 0.f, lb = 0.f;
    for (int b = threadIdx.x; b < NB; b += 1024) {
        float p = sc[b], q = sc[NB + b];
        lp += softplusf(-p);
        ln += softplusf(q);
        lb += softplusf(-(p - q));
    }
    sh0[threadIdx.x] = lp; sh1[threadIdx.x] = ln; sh2[threadIdx.x] = lb;
    __syncthreads();
    for (int o = 512; o; o >>= 1) {
        if (threadIdx.x < o) {
            sh0[threadIdx.x] += sh0[threadIdx.x + o];
            sh1[threadIdx.x] += sh1[threadIdx.x + o];
            sh2[threadIdx.x] += sh2[threadIdx.x + o];
        }
        __syncthreads();
    }
    if (threadIdx.x == 0) { sums[0] = sh0[0]; sums[1] = sh1[0]; sums[2] = sh2[0]; }
}

// ---------------- regularization sum of squares over 16 params ----------------
__global__ void k_reg(const float* p0, const float* p1, const float* p2, const float* p3,
                      const float* p4, const float* p5, const float* p6, const float* p7,
                      const float* p8, const float* p9, const float* p10, const float* p11,
                      const float* p12, const float* p13, const float* p14, const float* p15,
                      float* __restrict__ part)
{
    const float* ptrs[16] = {p0,p1,p2,p3,p4,p5,p6,p7,p8,p9,p10,p11,p12,p13,p14,p15};
    const int sz[16] = {NU*D, NI*D, D*D, 2*D, D*D, 2*D, 2*D*D, D,
                        D*D, D, D, 1, 2*D*D, D, D*D, D};
    int gid = blockIdx.x * blockDim.x + threadIdx.x;
    int gsz = gridDim.x * blockDim.x;
    float a = 0.f;
    #pragma unroll
    for (int s = 0; s < 16; s++) {
        const float* p = ptrs[s];
        int n = sz[s];
        for (int i = gid; i < n; i += gsz) { float v = p[i]; a += v * v; }
    }
    __shared__ float sh[256];
    sh[threadIdx.x] = a;
    __syncthreads();
    for (int o = 128; o; o >>= 1) {
        if (threadIdx.x < o) sh[threadIdx.x] += sh[threadIdx.x + o];
        __syncthreads();
    }
    if (threadIdx.x == 0) part[blockIdx.x] = sh[0];
}

__global__ void k_final(const float* __restrict__ part, const float* __restrict__ sums,
                        float* __restrict__ out)
{
    __shared__ float sh[256];
    sh[threadIdx.x] = part[threadIdx.x];
    __syncthreads();
    for (int o = 128; o; o >>= 1) {
        if (threadIdx.x < o) sh[threadIdx.x] += sh[threadIdx.x + o];
        __syncthreads();
    }
    if (threadIdx.x == 0) {
        float reg = sh[0] * 1e-7f;
        float lr = (sums[0] + sums[1] + sums[2]) / (float)NB;
        out[0] = reg + lr;
        out[1] = lr;
        out[2] = 0.f;
    }
}

// ---------------- host ----------------
extern "C" void kernel_launch(void* const* d_in, const int* in_sizes, int n_in,
                              void* d_out, int out_size)
{
    const float* E_g_0  = (const float*)d_in[0];
    const float* E_d_0  = (const float*)d_in[1];
    const float* att_W  = (const float*)d_in[2];
    const float* att_a  = (const float*)d_in[3];
    const float* att1_W = (const float*)d_in[4];
    const float* att1_a = (const float*)d_in[5];
    const float* W1     = (const float*)d_in[6];
    const float* b1     = (const float*)d_in[7];
    const float* W2     = (const float*)d_in[8];
    const float* b2     = (const float*)d_in[9];
    const float* W3     = (const float*)d_in[10];
    const float* b3     = (const float*)d_in[11];
    const float* M1     = (const float*)d_in[12];
    const float* mb1    = (const float*)d_in[13];
    const float* M2     = (const float*)d_in[14];
    const float* mb2    = (const float*)d_in[15];
    const float* adj_vals = (const float*)d_in[16];
    const int* uids = (const int*)d_in[17];
    const int* pos  = (const int*)d_in[19];
    const int* neg  = (const int*)d_in[20];
    const int* gene_edges = (const int*)d_in[21];
    const int* drug_edges = (const int*)d_in[22];
    const int* adj_rows = (const int*)d_in[23];
    const int* adj_cols = (const int*)d_in[24];
    const unsigned char* drop1 = (const unsigned char*)d_in[25];
    const unsigned char* drop2 = (const unsigned char*)d_in[26];
    float* out = (float*)d_out;

    float *p_h, *p_s1, *p_s2, *p_Ed0, *p_Eg0, *p_Eg, *p_Ed;
    float *p_h1, *p_h2, *p_sc, *p_part, *p_sums, *p_w;
    int *p_deg, *p_off, *p_cur, *p_eidx, *p_key, *p_srcA, *p_dw;
    unsigned char *p_need;
    cudaGetSymbolAddress((void**)&p_h, g_h);
    cudaGetSymbolAddress((void**)&p_s1, g_s1);
    cudaGetSymbolAddress((void**)&p_s2, g_s2);
    cudaGetSymbolAddress((void**)&p_Ed0, g_Ed0);
    cudaGetSymbolAddress((void**)&p_Eg0, g_Eg0);
    cudaGetSymbolAddress((void**)&p_Eg, g_Eg);
    cudaGetSymbolAddress((void**)&p_Ed, g_Ed);
    cudaGetSymbolAddress((void**)&p_deg, g_deg);
    cudaGetSymbolAddress((void**)&p_off, g_off);
    cudaGetSymbolAddress((void**)&p_cur, g_cur);
    cudaGetSymbolAddress((void**)&p_eidx, g_eidx);
    cudaGetSymbolAddress((void**)&p_w, g_w);
    cudaGetSymbolAddress((void**)&p_key, g_key);
    cudaGetSymbolAddress((void**)&p_srcA, g_srcA);
    cudaGetSymbolAddress((void**)&p_need, g_need);
    cudaGetSymbolAddress((void**)&p_h1, g_h1);
    cudaGetSymbolAddress((void**)&p_h2, g_h2);
    cudaGetSymbolAddress((void**)&p_sc, g_sc);
    cudaGetSymbolAddress((void**)&p_part, g_part);
    cudaGetSymbolAddress((void**)&p_sums, g_sums);
    cudaGetSymbolAddress((void**)&p_dw, g_dropWide);

    dim3 gGemmAtt(2, (NC + 127) / 128);       // 2 x 313, partial last tile
    dim3 gGemmMlp(2, (2 * NB + 127) / 128);   // 2 x 128, full tiles
    int rowBlocksC = (NC + 7) / 8;
    int eaBlocks = (EA + 255) / 256;
    int ezBlocks = (EZ + 255) / 256;
    int bBlocks  = (NB + 255) / 256;

    // ---- drop dtype detection ----
    k_dropdetect<<<1, 256>>>(drop1, p_dw);

    // ---- combined attention: h = [E_d_0; E_g_0] @ att_W (tf32 tensor cores) ----
    k_tf32gemm<1><<<gGemmAtt, 256>>>(E_d_0, E_g_0, nullptr, nullptr, nullptr,
                                     att_W, p_h, NC, D, D, nullptr, 0);
    k_rowdots<<<rowBlocksC, 256>>>(p_h, att_a, p_s1, p_s2, NC);

    // combined attention CSR, payload = src node id
    cudaMemsetAsync(p_deg, 0, NC * sizeof(int));
    k_keys_hist_att<<<eaBlocks, 256>>>(drug_edges, gene_edges, p_key, p_srcA, p_deg);
    k_scan<<<1, 1024>>>(p_deg, p_off, p_cur, NC);
    k_scatter_att<<<eaBlocks, 256>>>(p_key, p_srcA, p_cur, p_eidx);
    k_att_agg<<<rowBlocksC, 256>>>(E_d_0, E_g_0, p_s1, p_s2, p_h,
                                   p_off, p_eidx, p_Ed0, p_Eg0);

    // ---- needed-row mask ----
    cudaMemsetAsync(p_need, 0, NC);
    k_mark<<<bBlocks, 256>>>(uids, NB, 0, p_need);
    k_mark<<<bBlocks, 256>>>(pos,  NB, NN, p_need);
    k_mark<<<bBlocks, 256>>>(neg,  NB, NN, p_need);

    // ---- combined SPMM CSR ----
    cudaMemsetAsync(p_deg, 0, NC * sizeof(int));
    k_keys_hist_spmm<<<ezBlocks, 256>>>(adj_rows, adj_cols, p_key, p_deg);
    k_scan<<<1, 1024>>>(p_deg, p_off, p_cur, NC);
    k_scatter_spmm<<<ezBlocks, 256>>>(p_key, adj_rows, adj_cols, adj_vals,
                                      drop1, drop2, p_dw, p_cur, p_eidx, p_w);
    k_spmm<<<rowBlocksC, 256>>>(p_Ed0, p_Eg0, p_need, p_off, p_eidx, p_w,
                                p_Eg, p_Ed);

    // ---- fused pos+neg MLP (batch 2*NB), tf32 tensor cores ----
    k_tf32gemm<2><<<gGemmMlp, 256>>>(p_Eg, p_Ed, uids, pos, neg,
                                     W1, p_h1, 2 * NB, D, 2 * D, b1, 1);
    k_tf32gemm<0><<<gGemmMlp, 256>>>(p_h1, nullptr, nullptr, nullptr, nullptr,
                                     W2, p_h2, 2 * NB, D, D, b2, 1);
    k_dotw3<<<(2 * NB + 7) / 8, 256>>>(p_h2, W3, b3, p_sc, 2 * NB);

    // ---- losses ----
    k_loss<<<1, 1024>>>(p_sc, p_sums);
    k_reg<<<256, 256>>>(E_g_0, E_d_0, att_W, att_a, att1_W, att1_a, W1, b1,
                        W2, b2, W3, b3, M1, mb1, M2, mb2, p_part);
    k_final<<<1, 256>>>(p_part, p_sums, out);
}